// round 1
// baseline (speedup 1.0000x reference)
#include <cuda_runtime.h>

#define NN 20000
#define EE 320000
#define EP (EE + NN)
#define TT 24
#define SDIM 16
#define DDIM 8
#define HID 128
#define NL 3

typedef unsigned long long u64;

// ---------------- scratch (device globals; no allocations allowed) ----------
__device__ float g_h[NN * HID];
__device__ float g_xp[NN * HID];
__device__ float g_asrc[NN * 4];
__device__ float g_adst[NN * 4];
__device__ int   g_deg[NN];
__device__ int   g_rowptr[NN + 1];
__device__ int   g_fill[NN];
__device__ int   g_csrsrc[EP];
__device__ float g_h0[NN * HID];
__device__ float g_c0[NN * HID];
__device__ float g_h1[NN * HID];
__device__ float g_c1[NN * HID];
__device__ float g_z[NN * 512];
__device__ float g_WT0i[HID * 512];
__device__ float g_WT0h[HID * 512];
__device__ float g_WT1i[HID * 512];
__device__ float g_WT1h[HID * 512];
__device__ float g_b0[512];
__device__ float g_b1[512];

// ---------------- packed f32x2 helpers (Blackwell FFMA2 path) ---------------
__device__ __forceinline__ u64 pack2(float x, float y) {
    u64 r;
    asm("mov.b64 %0, {%1, %2};" : "=l"(r)
        : "r"(__float_as_uint(x)), "r"(__float_as_uint(y)));
    return r;
}
__device__ __forceinline__ void unpack2(u64 v, float& x, float& y) {
    unsigned a, b;
    asm("mov.b64 {%0, %1}, %2;" : "=r"(a), "=r"(b) : "l"(v));
    x = __uint_as_float(a);
    y = __uint_as_float(b);
}
__device__ __forceinline__ u64 ffma2(u64 a, u64 b, u64 c) {
    u64 d;
    asm("fma.rn.f32x2 %0, %1, %2, %3;" : "=l"(d) : "l"(a), "l"(b), "l"(c));
    return d;
}

// ---------------- setup kernels ---------------------------------------------
__global__ void k_init() {
    int idx = blockIdx.x * 256 + threadIdx.x;
    if (idx < NN * HID) {
        g_h0[idx] = 0.f; g_c0[idx] = 0.f;
        g_h1[idx] = 0.f; g_c1[idx] = 0.f;
    }
    if (idx < NN) { g_deg[idx] = 1; g_fill[idx] = 0; }  // 1 = self loop
}

__global__ void k_count(const int* __restrict__ ei) {
    int i = blockIdx.x * 256 + threadIdx.x;
    if (i < EE) atomicAdd(&g_deg[ei[EE + i]], 1);
}

__global__ void k_scan() {
    __shared__ int s[1024];
    int tid = threadIdx.x;
    int run = 0;
    for (int base = 0; base < NN; base += 1024) {
        int v = (base + tid < NN) ? g_deg[base + tid] : 0;
        s[tid] = v;
        __syncthreads();
        for (int off = 1; off < 1024; off <<= 1) {
            int t = (tid >= off) ? s[tid - off] : 0;
            __syncthreads();
            s[tid] += t;
            __syncthreads();
        }
        if (base + tid < NN) g_rowptr[base + tid] = run + s[tid] - v;
        run += s[1023];
        __syncthreads();
    }
    if (tid == 0) g_rowptr[NN] = run;
}

__global__ void k_fill(const int* __restrict__ ei) {
    int i = blockIdx.x * 256 + threadIdx.x;
    if (i >= EP) return;
    int s, d;
    if (i < EE) { s = ei[i]; d = ei[EE + i]; }
    else        { s = d = i - EE; }
    int p = atomicAdd(&g_fill[d], 1);
    g_csrsrc[g_rowptr[d] + p] = s;
}

__global__ void k_prep(const float* __restrict__ Wih0, const float* __restrict__ Whh0,
                       const float* __restrict__ Wih1, const float* __restrict__ Whh1,
                       const float* __restrict__ bih0, const float* __restrict__ bhh0,
                       const float* __restrict__ bih1, const float* __restrict__ bhh1) {
    int idx = blockIdx.x * 256 + threadIdx.x;
    if (idx < 512 * 128) {
        int j = idx >> 7, k = idx & 127;
        g_WT0i[k * 512 + j] = Wih0[idx];
        g_WT0h[k * 512 + j] = Whh0[idx];
        g_WT1i[k * 512 + j] = Wih1[idx];
        g_WT1h[k * 512 + j] = Whh1[idx];
    }
    if (idx < 512) {
        g_b0[idx] = bih0[idx] + bhh0[idx];
        g_b1[idx] = bih1[idx] + bhh1[idx];
    }
}

// ---------------- projection: h = [x_s, x_d] @ W + b ------------------------
__global__ void __launch_bounds__(256) k_proj(const float* __restrict__ xs,
                                              const float* __restrict__ xd,
                                              const float* __restrict__ W,
                                              const float* __restrict__ b) {
    __shared__ float Ws[24 * 128];
    __shared__ float sIn[16 * 24];
    int tid = threadIdx.x;
    int n0 = blockIdx.x * 16;
    for (int i = tid; i < 24 * 128; i += 256) Ws[i] = W[i];
    for (int i = tid; i < 16 * 24; i += 256) {
        int node = i / 24, k = i % 24;
        int gn = n0 + node;
        sIn[i] = (k < SDIM) ? xs[gn * SDIM + k] : xd[gn * DDIM + (k - SDIM)];
    }
    __syncthreads();
    int col = tid & 127;
    int half = tid >> 7;
    float bc = b[col];
    #pragma unroll
    for (int i = 0; i < 8; i++) {
        int n = half * 8 + i;
        float acc = bc;
        #pragma unroll
        for (int k = 0; k < 24; k++) acc += sIn[n * 24 + k] * Ws[k * 128 + col];
        g_h[(n0 + n) * HID + col] = acc;
    }
}

// ---------------- GAT GEMM: xp = h @ W  (M=NN, N=128, K=128) ----------------
__global__ void __launch_bounds__(256) k_gemm_gat(const float* __restrict__ B) {
    __shared__ float As[8][132];
    __shared__ float Bs[8][132];
    int bm0 = blockIdx.x * 128;
    int tid = threadIdx.x;
    int tx = tid & 15, ty = tid >> 4;
    int lr = tid >> 1;
    int lk = (tid & 1) * 4;
    int bk = tid >> 5;
    int bn = (tid & 31) * 4;
    u64 acc[8][4];
    #pragma unroll
    for (int r = 0; r < 8; r++)
        #pragma unroll
        for (int c = 0; c < 4; c++) acc[r][c] = 0ULL;

    for (int kt = 0; kt < 16; kt++) {
        int k0 = kt * 8;
        float4 av = make_float4(0.f, 0.f, 0.f, 0.f);
        int row = bm0 + lr;
        if (row < NN) av = *(const float4*)&g_h[row * 128 + k0 + lk];
        As[lk + 0][lr] = av.x; As[lk + 1][lr] = av.y;
        As[lk + 2][lr] = av.z; As[lk + 3][lr] = av.w;
        float4 bv = *(const float4*)&B[(k0 + bk) * 128 + bn];
        *(float4*)&Bs[bk][bn] = bv;
        __syncthreads();
        #pragma unroll
        for (int k = 0; k < 8; k++) {
            float4 a0 = *(float4*)&As[k][ty * 4];
            float4 a1 = *(float4*)&As[k][64 + ty * 4];
            float4 b0 = *(float4*)&Bs[k][tx * 4];
            float4 b1 = *(float4*)&Bs[k][64 + tx * 4];
            u64 bb[4] = { pack2(b0.x, b0.y), pack2(b0.z, b0.w),
                          pack2(b1.x, b1.y), pack2(b1.z, b1.w) };
            float am[8] = {a0.x, a0.y, a0.z, a0.w, a1.x, a1.y, a1.z, a1.w};
            #pragma unroll
            for (int r = 0; r < 8; r++) {
                u64 ar = pack2(am[r], am[r]);
                acc[r][0] = ffma2(ar, bb[0], acc[r][0]);
                acc[r][1] = ffma2(ar, bb[1], acc[r][1]);
                acc[r][2] = ffma2(ar, bb[2], acc[r][2]);
                acc[r][3] = ffma2(ar, bb[3], acc[r][3]);
            }
        }
        __syncthreads();
    }
    #pragma unroll
    for (int r = 0; r < 8; r++) {
        int row = bm0 + ((r < 4) ? ty * 4 + r : 64 + ty * 4 + (r - 4));
        if (row >= NN) continue;
        #pragma unroll
        for (int c = 0; c < 4; c++) {
            float x, y;
            unpack2(acc[r][c], x, y);
            int col = (c < 2) ? tx * 4 + c * 2 : 64 + tx * 4 + (c - 2) * 2;
            g_xp[row * 128 + col] = x;
            g_xp[row * 128 + col + 1] = y;
        }
    }
}

// ---------------- attention score kernel ------------------------------------
__global__ void k_att(const float* __restrict__ asv, const float* __restrict__ adv) {
    int w = threadIdx.x >> 5, lane = threadIdx.x & 31;
    int n = blockIdx.x * 8 + w;
    if (n >= NN) return;
    float4 x = *(const float4*)&g_xp[n * 128 + lane * 4];
    float4 s = *(const float4*)&asv[lane * 4];
    float4 d = *(const float4*)&adv[lane * 4];
    float ps = x.x * s.x + x.y * s.y + x.z * s.z + x.w * s.w;
    float pd = x.x * d.x + x.y * d.y + x.z * d.z + x.w * d.w;
    #pragma unroll
    for (int o = 1; o < 8; o <<= 1) {
        ps += __shfl_xor_sync(0xffffffffu, ps, o);
        pd += __shfl_xor_sync(0xffffffffu, pd, o);
    }
    if ((lane & 7) == 0) {
        g_asrc[n * 4 + (lane >> 3)] = ps;
        g_adst[n * 4 + (lane >> 3)] = pd;
    }
}

// ---------------- segment softmax + aggregate + bias + residual + LN + ReLU -
__global__ void __launch_bounds__(256) k_aggr(const float* __restrict__ gb,
                                              const float* __restrict__ lg,
                                              const float* __restrict__ lb) {
    int w = threadIdx.x >> 5, lane = threadIdx.x & 31;
    int n = blockIdx.x * 8 + w;
    if (n >= NN) return;
    int h = lane >> 3;       // head owning this lane's 4 output columns
    int hh = lane & 3;       // head handled in pass-1 by this lane
    int s0 = g_rowptr[n], s1 = g_rowptr[n + 1];

    // pass 1: per-head max over in-edges (8 edges in parallel, 4 lanes each)
    float adhh = g_adst[n * 4 + hh];
    float mx = -1e30f;
    for (int i = s0 + (lane >> 2); i < s1; i += 8) {
        int s = g_csrsrc[i];
        float v = g_asrc[s * 4 + hh] + adhh;
        v = v > 0.f ? v : 0.2f * v;
        mx = fmaxf(mx, v);
    }
    mx = fmaxf(mx, __shfl_xor_sync(0xffffffffu, mx, 4));
    mx = fmaxf(mx, __shfl_xor_sync(0xffffffffu, mx, 8));
    mx = fmaxf(mx, __shfl_xor_sync(0xffffffffu, mx, 16));
    float m_h = __shfl_sync(0xffffffffu, mx, h);     // max for my head
    float ad_h = __shfl_sync(0xffffffffu, adhh, h);  // a_dst for my head

    // pass 2: exp / denom / weighted message accumulation
    float4 acc = make_float4(0.f, 0.f, 0.f, 0.f);
    float denom = 0.f;
    for (int i = s0; i < s1; i++) {
        int s = g_csrsrc[i];
        float v = g_asrc[s * 4 + h] + ad_h;
        v = v > 0.f ? v : 0.2f * v;
        float ex = __expf(v - m_h);
        denom += ex;
        float4 xv = *(const float4*)&g_xp[s * 128 + lane * 4];
        acc.x += ex * xv.x; acc.y += ex * xv.y;
        acc.z += ex * xv.z; acc.w += ex * xv.w;
    }
    float inv = 1.f / (denom + 1e-16f);
    int j = lane * 4;
    float4 hv = *(const float4*)&g_h[n * 128 + j];
    float4 bv = *(const float4*)&gb[j];
    float4 o;
    o.x = acc.x * inv + bv.x + hv.x;
    o.y = acc.y * inv + bv.y + hv.y;
    o.z = acc.z * inv + bv.z + hv.z;
    o.w = acc.w * inv + bv.w + hv.w;
    // LayerNorm over 128 features (warp-wide)
    float sm = o.x + o.y + o.z + o.w;
    #pragma unroll
    for (int q = 16; q; q >>= 1) sm += __shfl_xor_sync(0xffffffffu, sm, q);
    float mu = sm * (1.f / 128.f);
    float dx = o.x - mu, dy = o.y - mu, dz = o.z - mu, dw = o.w - mu;
    float sq = dx * dx + dy * dy + dz * dz + dw * dw;
    #pragma unroll
    for (int q = 16; q; q >>= 1) sq += __shfl_xor_sync(0xffffffffu, sq, q);
    float rs = rsqrtf(sq * (1.f / 128.f) + 1e-5f);
    float4 gv = *(const float4*)&lg[j];
    float4 bb = *(const float4*)&lb[j];
    o.x = fmaxf(gv.x * dx * rs + bb.x, 0.f);
    o.y = fmaxf(gv.y * dy * rs + bb.y, 0.f);
    o.z = fmaxf(gv.z * dz * rs + bb.z, 0.f);
    o.w = fmaxf(gv.w * dw * rs + bb.w, 0.f);
    *(float4*)&g_h[n * 128 + j] = o;
}

// ---------------- LSTM fused GEMM: z = x@WihT + h@WhhT + bias ---------------
__global__ void __launch_bounds__(256) k_lstm_gemm(int cell) {
    const float* Ax = cell ? g_h0 : g_h;
    const float* Ah = cell ? g_h1 : g_h0;
    const float* B1 = cell ? g_WT1i : g_WT0i;
    const float* B2 = cell ? g_WT1h : g_WT0h;
    const float* bias = cell ? g_b1 : g_b0;

    __shared__ float As[8][132];
    __shared__ float Bs[8][132];
    int bm0 = blockIdx.x * 128;
    int bn0 = blockIdx.y * 128;
    int tid = threadIdx.x;
    int tx = tid & 15, ty = tid >> 4;
    int lr = tid >> 1;
    int lk = (tid & 1) * 4;
    int bk = tid >> 5;
    int bn = (tid & 31) * 4;
    u64 acc[8][4];
    #pragma unroll
    for (int r = 0; r < 8; r++)
        #pragma unroll
        for (int c = 0; c < 4; c++) acc[r][c] = 0ULL;

    for (int kt = 0; kt < 32; kt++) {
        const float* A = (kt < 16) ? Ax : Ah;
        const float* B = (kt < 16) ? B1 : B2;
        int k0 = (kt & 15) * 8;
        float4 av = make_float4(0.f, 0.f, 0.f, 0.f);
        int row = bm0 + lr;
        if (row < NN) av = *(const float4*)&A[row * 128 + k0 + lk];
        As[lk + 0][lr] = av.x; As[lk + 1][lr] = av.y;
        As[lk + 2][lr] = av.z; As[lk + 3][lr] = av.w;
        float4 bv = *(const float4*)&B[(k0 + bk) * 512 + bn0 + bn];
        *(float4*)&Bs[bk][bn] = bv;
        __syncthreads();
        #pragma unroll
        for (int k = 0; k < 8; k++) {
            float4 a0 = *(float4*)&As[k][ty * 4];
            float4 a1 = *(float4*)&As[k][64 + ty * 4];
            float4 b0 = *(float4*)&Bs[k][tx * 4];
            float4 b1 = *(float4*)&Bs[k][64 + tx * 4];
            u64 bb[4] = { pack2(b0.x, b0.y), pack2(b0.z, b0.w),
                          pack2(b1.x, b1.y), pack2(b1.z, b1.w) };
            float am[8] = {a0.x, a0.y, a0.z, a0.w, a1.x, a1.y, a1.z, a1.w};
            #pragma unroll
            for (int r = 0; r < 8; r++) {
                u64 ar = pack2(am[r], am[r]);
                acc[r][0] = ffma2(ar, bb[0], acc[r][0]);
                acc[r][1] = ffma2(ar, bb[1], acc[r][1]);
                acc[r][2] = ffma2(ar, bb[2], acc[r][2]);
                acc[r][3] = ffma2(ar, bb[3], acc[r][3]);
            }
        }
        __syncthreads();
    }
    #pragma unroll
    for (int r = 0; r < 8; r++) {
        int row = bm0 + ((r < 4) ? ty * 4 + r : 64 + ty * 4 + (r - 4));
        if (row >= NN) continue;
        #pragma unroll
        for (int c = 0; c < 4; c++) {
            float x, y;
            unpack2(acc[r][c], x, y);
            int col = (c < 2) ? tx * 4 + c * 2 : 64 + tx * 4 + (c - 2) * 2;
            g_z[row * 512 + bn0 + col]     = x + bias[bn0 + col];
            g_z[row * 512 + bn0 + col + 1] = y + bias[bn0 + col + 1];
        }
    }
}

// ---------------- LSTM gate nonlinearity ------------------------------------
__global__ void k_gates(int cell) {
    int idx = blockIdx.x * 256 + threadIdx.x;
    if (idx >= NN * HID) return;
    float* hq = cell ? g_h1 : g_h0;
    float* cq = cell ? g_c1 : g_c0;
    int n = idx >> 7, j = idx & 127;
    const float* z = g_z + n * 512 + j;
    float zi = z[0], zf = z[128], zg = z[256], zo = z[384];
    float si = 1.f / (1.f + __expf(-zi));
    float sf = 1.f / (1.f + __expf(-zf));
    float so = 1.f / (1.f + __expf(-zo));
    float tg = tanhf(zg);
    float c = sf * cq[idx] + si * tg;
    float hh = so * tanhf(c);
    cq[idx] = c;
    hq[idx] = hh;
}

// ---------------- output head -----------------------------------------------
__global__ void k_out(const float* __restrict__ W1, const float* __restrict__ b1,
                      const float* __restrict__ W2, const float* __restrict__ b2,
                      float* __restrict__ out) {
    int w = threadIdx.x >> 5, lane = threadIdx.x & 31;
    int n = blockIdx.x * 8 + w;
    if (n >= NN) return;
    float a0 = b1[lane], a1 = b1[lane + 32];
    const float* hp = g_h1 + n * 128;
    #pragma unroll 4
    for (int k = 0; k < 128; k++) {
        float hk = hp[k];
        a0 += hk * W1[k * 64 + lane];
        a1 += hk * W1[k * 64 + lane + 32];
    }
    float s = fmaxf(a0, 0.f) * W2[lane] + fmaxf(a1, 0.f) * W2[lane + 32];
    #pragma unroll
    for (int q = 16; q; q >>= 1) s += __shfl_xor_sync(0xffffffffu, s, q);
    if (lane == 0) out[n] = s + b2[0];
}

// ---------------- driver -----------------------------------------------------
extern "C" void kernel_launch(void* const* d_in, const int* in_sizes, int n_in,
                              void* d_out, int out_size) {
    const float* xs    = (const float*)d_in[0];
    const float* xd    = (const float*)d_in[1];
    const int*   ei    = (const int*)d_in[2];
    const float* projW = (const float*)d_in[3];
    const float* projb = (const float*)d_in[4];
    const float* gatW  = (const float*)d_in[5];
    const float* attS  = (const float*)d_in[6];
    const float* attD  = (const float*)d_in[7];
    const float* gatb  = (const float*)d_in[8];
    const float* lng   = (const float*)d_in[9];
    const float* lnb   = (const float*)d_in[10];
    const float* Wih0  = (const float*)d_in[11];
    const float* Whh0  = (const float*)d_in[12];
    const float* bih0  = (const float*)d_in[13];
    const float* bhh0  = (const float*)d_in[14];
    const float* Wih1  = (const float*)d_in[15];
    const float* Whh1  = (const float*)d_in[16];
    const float* bih1  = (const float*)d_in[17];
    const float* bhh1  = (const float*)d_in[18];
    const float* oW1   = (const float*)d_in[19];
    const float* ob1   = (const float*)d_in[20];
    const float* oW2   = (const float*)d_in[21];
    const float* ob2   = (const float*)d_in[22];
    float* out = (float*)d_out;

    k_init<<<(NN * HID + 255) / 256, 256>>>();
    k_count<<<(EE + 255) / 256, 256>>>(ei);
    k_scan<<<1, 1024>>>();
    k_fill<<<(EP + 255) / 256, 256>>>(ei);
    k_prep<<<(512 * 128 + 255) / 256, 256>>>(Wih0, Whh0, Wih1, Whh1,
                                             bih0, bhh0, bih1, bhh1);

    for (int t = 0; t < TT; t++) {
        k_proj<<<NN / 16, 256>>>(xs, xd + (size_t)t * NN * DDIM, projW, projb);
        for (int l = 0; l < NL; l++) {
            k_gemm_gat<<<(NN + 127) / 128, 256>>>(gatW + l * HID * HID);
            k_att<<<(NN + 7) / 8, 256>>>(attS + l * HID, attD + l * HID);
            k_aggr<<<(NN + 7) / 8, 256>>>(gatb + l * HID, lng + l * HID, lnb + l * HID);
        }
        k_lstm_gemm<<<dim3((NN + 127) / 128, 4), 256>>>(0);
        k_gates<<<(NN * HID + 255) / 256, 256>>>(0);
        k_lstm_gemm<<<dim3((NN + 127) / 128, 4), 256>>>(1);
        k_gates<<<(NN * HID + 255) / 256, 256>>>(1);
    }
    k_out<<<(NN + 7) / 8, 256>>>(oW1, ob1, oW2, ob2, out);
}

// round 3
// speedup vs baseline: 1.6106x; 1.6106x over previous
#include <cuda_runtime.h>
#include <cuda_bf16.h>

#define NN 20000
#define EE 320000
#define EP (EE + NN)
#define TT 24
#define SDIM 16
#define DDIM 8
#define HID 128
#define NL 3

typedef unsigned long long u64;

// ---------------- scratch (device globals; no allocations allowed) ----------
__device__ float g_h[NN * HID];
__device__ float g_xp[NN * HID];
__device__ float g_asrc[NN * 4];
__device__ float g_adst[NN * 4];
__device__ int   g_deg[NN];
__device__ int   g_rowptr[NN + 1];
__device__ int   g_fill[NN];
__device__ int   g_csrsrc[EP];
__device__ float g_h0[NN * HID];
__device__ float g_c0[NN * HID];
__device__ float g_h1[NN * HID];
__device__ float g_c1[NN * HID];
__device__ float g_z[NN * 512];
__device__ float g_b0[512];
__device__ float g_b1[512];
// bf16 split weights: B stored [Nrows][K] K-major (D = A @ B^T)
__device__ __nv_bfloat16 g_BGhi[NL][128 * 128];
__device__ __nv_bfloat16 g_BGlo[NL][128 * 128];
__device__ __nv_bfloat16 g_BLhi[2][512 * 256];
__device__ __nv_bfloat16 g_BLlo[2][512 * 256];

// ---------------- helpers ----------------------------------------------------
__device__ __forceinline__ unsigned smem_u32(const void* p) {
    unsigned a;
    asm("{ .reg .u64 t; cvta.to.shared.u64 t, %1; cvt.u32.u64 %0, t; }"
        : "=r"(a) : "l"(p));
    return a;
}
__device__ __forceinline__ void ldm4(unsigned* r, unsigned addr) {
    asm volatile("ldmatrix.sync.aligned.m8n8.x4.shared.b16 {%0,%1,%2,%3}, [%4];"
        : "=r"(r[0]), "=r"(r[1]), "=r"(r[2]), "=r"(r[3]) : "r"(addr));
}
__device__ __forceinline__ void mma16816(float* c, const unsigned* a, const unsigned* b) {
    asm volatile(
        "mma.sync.aligned.m16n8k16.row.col.f32.bf16.bf16.f32 "
        "{%0,%1,%2,%3}, {%4,%5,%6,%7}, {%8,%9}, {%0,%1,%2,%3};"
        : "+f"(c[0]), "+f"(c[1]), "+f"(c[2]), "+f"(c[3])
        : "r"(a[0]), "r"(a[1]), "r"(a[2]), "r"(a[3]), "r"(b[0]), "r"(b[1]));
}
__device__ __forceinline__ unsigned short f2bf(float x) {
    __nv_bfloat16 b = __float2bfloat16_rn(x);
    return reinterpret_cast<unsigned short&>(b);
}
__device__ __forceinline__ float bf2f(unsigned short u) {
    __nv_bfloat16 b = reinterpret_cast<__nv_bfloat16&>(u);
    return __bfloat162float(b);
}

// ---------------- setup kernels ---------------------------------------------
__global__ void k_init() {
    int idx = blockIdx.x * 256 + threadIdx.x;
    if (idx < NN * HID) {
        g_h0[idx] = 0.f; g_c0[idx] = 0.f;
        g_h1[idx] = 0.f; g_c1[idx] = 0.f;
    }
    if (idx < NN) { g_deg[idx] = 1; g_fill[idx] = 0; }
}

__global__ void k_count(const int* __restrict__ ei) {
    int i = blockIdx.x * 256 + threadIdx.x;
    if (i < EE) atomicAdd(&g_deg[ei[EE + i]], 1);
}

__global__ void k_scan() {
    __shared__ int s[1024];
    int tid = threadIdx.x;
    int run = 0;
    for (int base = 0; base < NN; base += 1024) {
        int v = (base + tid < NN) ? g_deg[base + tid] : 0;
        s[tid] = v;
        __syncthreads();
        for (int off = 1; off < 1024; off <<= 1) {
            int t = (tid >= off) ? s[tid - off] : 0;
            __syncthreads();
            s[tid] += t;
            __syncthreads();
        }
        if (base + tid < NN) g_rowptr[base + tid] = run + s[tid] - v;
        run += s[1023];
        __syncthreads();
    }
    if (tid == 0) g_rowptr[NN] = run;
}

__global__ void k_fill(const int* __restrict__ ei) {
    int i = blockIdx.x * 256 + threadIdx.x;
    if (i >= EP) return;
    int s, d;
    if (i < EE) { s = ei[i]; d = ei[EE + i]; }
    else        { s = d = i - EE; }
    int p = atomicAdd(&g_fill[d], 1);
    g_csrsrc[g_rowptr[d] + p] = s;
}

__global__ void k_prep_lstm(const float* __restrict__ Wih0, const float* __restrict__ Whh0,
                            const float* __restrict__ Wih1, const float* __restrict__ Whh1,
                            const float* __restrict__ bih0, const float* __restrict__ bhh0,
                            const float* __restrict__ bih1, const float* __restrict__ bhh1) {
    int idx = blockIdx.x * 256 + threadIdx.x;
    if (idx < 512 * 256) {
        int n = idx >> 8, k = idx & 255;
        float v0 = (k < 128) ? Wih0[n * 128 + k] : Whh0[n * 128 + (k - 128)];
        float v1 = (k < 128) ? Wih1[n * 128 + k] : Whh1[n * 128 + (k - 128)];
        unsigned short h0 = f2bf(v0), h1 = f2bf(v1);
        g_BLhi[0][idx] = reinterpret_cast<__nv_bfloat16&>(h0);
        g_BLhi[1][idx] = reinterpret_cast<__nv_bfloat16&>(h1);
        unsigned short l0 = f2bf(v0 - bf2f(h0)), l1 = f2bf(v1 - bf2f(h1));
        g_BLlo[0][idx] = reinterpret_cast<__nv_bfloat16&>(l0);
        g_BLlo[1][idx] = reinterpret_cast<__nv_bfloat16&>(l1);
    }
    if (idx < 512) {
        g_b0[idx] = bih0[idx] + bhh0[idx];
        g_b1[idx] = bih1[idx] + bhh1[idx];
    }
}

__global__ void k_prep_gat(const float* __restrict__ gatW) {
    int idx = blockIdx.x * 256 + threadIdx.x;
    if (idx >= NL * 128 * 128) return;
    int l = idx >> 14, rem = idx & 16383;
    int j = rem >> 7, k = rem & 127;                    // B[j][k] = W[k][j]
    float v = gatW[l * 16384 + k * 128 + j];
    unsigned short h = f2bf(v);
    unsigned short lo = f2bf(v - bf2f(h));
    g_BGhi[l][rem] = reinterpret_cast<__nv_bfloat16&>(h);
    g_BGlo[l][rem] = reinterpret_cast<__nv_bfloat16&>(lo);
}

// ---------------- projection: h = [x_s, x_d] @ W + b ------------------------
__global__ void __launch_bounds__(256) k_proj(const float* __restrict__ xs,
                                              const float* __restrict__ xd,
                                              const float* __restrict__ W,
                                              const float* __restrict__ b) {
    __shared__ float Ws[24 * 128];
    __shared__ float sIn[16 * 24];
    int tid = threadIdx.x;
    int n0 = blockIdx.x * 16;
    for (int i = tid; i < 24 * 128; i += 256) Ws[i] = W[i];
    for (int i = tid; i < 16 * 24; i += 256) {
        int node = i / 24, k = i % 24;
        int gn = n0 + node;
        sIn[i] = (k < SDIM) ? xs[gn * SDIM + k] : xd[gn * DDIM + (k - SDIM)];
    }
    __syncthreads();
    int col = tid & 127;
    int half = tid >> 7;
    float bc = b[col];
    #pragma unroll
    for (int i = 0; i < 8; i++) {
        int n = half * 8 + i;
        float acc = bc;
        #pragma unroll
        for (int k = 0; k < 24; k++) acc += sIn[n * 24 + k] * Ws[k * 128 + col];
        g_h[(n0 + n) * HID + col] = acc;
    }
}

// ---------------- unified HMMA bf16-split GEMM ------------------------------
// mode 0 (GAT):  D = h @ Wgat^T  -> g_xp  + fused att_src/att_dst dots
// mode 1 (LSTM): D = x @ Wih^T + h @ Whh^T + bias -> g_z slice
// D = A@B^T with A fp32 split on the fly; 3 products: AhBh + AhBl + AlBh.
#define PITCH 40   // bf16 elements per SMEM row (80 B): conflict-free ldmatrix

__global__ void __launch_bounds__(256)
k_mma(int mode, int sel, const float* __restrict__ av0, const float* __restrict__ av1) {
    __shared__ __align__(16) __nv_bfloat16 sAh[128 * PITCH];
    __shared__ __align__(16) __nv_bfloat16 sAl[128 * PITCH];
    __shared__ __align__(16) __nv_bfloat16 sBh[128 * PITCH];
    __shared__ __align__(16) __nv_bfloat16 sBl[128 * PITCH];
    __shared__ float s_vec[256];

    const int tid = threadIdx.x;
    const int wid = tid >> 5;
    const int lane = tid & 31;
    const int warpm = wid >> 1;       // 0..3  (32 rows each)
    const int warpn = wid & 1;        // 0..1  (64 cols each)
    const int bm0 = blockIdx.x * 128;
    const int bn0 = blockIdx.y * 128;

    const int nchunks = mode ? 8 : 4;           // K chunks of 32
    const int ldB = mode ? 256 : 128;
    const float* A0;
    const float* A1;
    const __nv_bfloat16* Bh;
    const __nv_bfloat16* Bl;
    if (mode == 0) {
        A0 = g_h; A1 = g_h;
        Bh = g_BGhi[sel]; Bl = g_BGlo[sel];
    } else {
        A0 = sel ? g_h0 : g_h;
        A1 = sel ? g_h1 : g_h0;
        Bh = g_BLhi[sel]; Bl = g_BLlo[sel];
    }

    // per-CTA vectors
    if (mode == 0) {
        if (tid < 128) s_vec[tid] = av0[tid];
        else           s_vec[tid] = av1[tid - 128];
    } else {
        const float* bias = sel ? g_b1 : g_b0;
        if (tid < 128) s_vec[tid] = bias[bn0 + tid];
    }

    const unsigned uAh = smem_u32(sAh), uAl = smem_u32(sAl);
    const unsigned uBh = smem_u32(sBh), uBl = smem_u32(sBl);

    // ldmatrix lane addressing (byte offsets into padded [row][PITCH] layout)
    const unsigned a_row = (unsigned)(warpm * 32 + (lane & 15)) * (PITCH * 2);
    const unsigned a_k   = (unsigned)((lane >> 4) * 8) * 2;
    const unsigned b_row = (unsigned)(warpn * 64 + (lane & 7) + ((lane >= 16) ? 8 : 0)) * (PITCH * 2);
    const unsigned b_k   = (unsigned)(((lane >> 3) & 1) * 8) * 2;

    float acc[2][8][4];
    #pragma unroll
    for (int mt = 0; mt < 2; mt++)
        #pragma unroll
        for (int nt = 0; nt < 8; nt++)
            #pragma unroll
            for (int i = 0; i < 4; i++) acc[mt][nt][i] = 0.f;

    const int lr = tid >> 1;          // loader row 0..127
    const int lj = tid & 1;           // loader half (16 elems)

    for (int c = 0; c < nchunks; c++) {
        const float* Ab = (c < nchunks / 2 || mode == 0) ? A0 : A1;
        if (mode == 1 && c >= 4) Ab = A1;
        const int kofsA = mode ? (c & 3) * 32 : c * 32;
        const int kb = c * 32;

        // ---- A: load fp32, split to hi/lo bf16 ----
        {
            int row = bm0 + lr;
            float v[16];
            if (row < NN) {
                const float4* src = (const float4*)&Ab[(size_t)row * 128 + kofsA + lj * 16];
                #pragma unroll
                for (int q = 0; q < 4; q++) {
                    float4 p = src[q];
                    v[q * 4 + 0] = p.x; v[q * 4 + 1] = p.y;
                    v[q * 4 + 2] = p.z; v[q * 4 + 3] = p.w;
                }
            } else {
                #pragma unroll
                for (int i = 0; i < 16; i++) v[i] = 0.f;
            }
            union { uint4 q[2]; unsigned short s[16]; } uh, ul;
            #pragma unroll
            for (int i = 0; i < 16; i++) {
                unsigned short h = f2bf(v[i]);
                uh.s[i] = h;
                ul.s[i] = f2bf(v[i] - bf2f(h));
            }
            int so = lr * PITCH + lj * 16;
            *(uint4*)&sAh[so] = uh.q[0]; *(uint4*)&sAh[so + 8] = uh.q[1];
            *(uint4*)&sAl[so] = ul.q[0]; *(uint4*)&sAl[so + 8] = ul.q[1];
        }
        // ---- B: already bf16 hi/lo ----
        {
            size_t gb = (size_t)(bn0 + lr) * ldB + kb + lj * 16;
            int so = lr * PITCH + lj * 16;
            uint4 q0 = *(const uint4*)&Bh[gb];
            uint4 q1 = *(const uint4*)&Bh[gb + 8];
            *(uint4*)&sBh[so] = q0; *(uint4*)&sBh[so + 8] = q1;
            uint4 r0 = *(const uint4*)&Bl[gb];
            uint4 r1 = *(const uint4*)&Bl[gb + 8];
            *(uint4*)&sBl[so] = r0; *(uint4*)&sBl[so + 8] = r1;
        }
        __syncthreads();

        #pragma unroll
        for (int s = 0; s < 2; s++) {
            unsigned ah[2][4], al[2][4], bhf[4][4], blf[4][4];
            unsigned ka = (unsigned)(s * 32) + a_k;
            unsigned kbb = (unsigned)(s * 32) + b_k;
            #pragma unroll
            for (int mt = 0; mt < 2; mt++) {
                unsigned ao = a_row + (unsigned)(mt * 16 * PITCH * 2) + ka;
                ldm4(ah[mt], uAh + ao);
                ldm4(al[mt], uAl + ao);
            }
            #pragma unroll
            for (int pr = 0; pr < 4; pr++) {
                unsigned bo = b_row + (unsigned)(pr * 16 * PITCH * 2) + kbb;
                ldm4(bhf[pr], uBh + bo);
                ldm4(blf[pr], uBl + bo);
            }
            #pragma unroll
            for (int mt = 0; mt < 2; mt++)
                #pragma unroll
                for (int nt = 0; nt < 8; nt++) {
                    const unsigned* bH = &bhf[nt >> 1][(nt & 1) * 2];
                    const unsigned* bL = &blf[nt >> 1][(nt & 1) * 2];
                    mma16816(acc[mt][nt], ah[mt], bH);   // Ah*Bh
                    mma16816(acc[mt][nt], ah[mt], bL);   // Ah*Bl
                    mma16816(acc[mt][nt], al[mt], bH);   // Al*Bh
                }
        }
        __syncthreads();
    }

    // ---- epilogue ----
    const int rbase = bm0 + warpm * 32 + (lane >> 2);
    const int cbase = warpn * 64 + 2 * (lane & 3);
    if (mode == 1) {
        #pragma unroll
        for (int mt = 0; mt < 2; mt++)
            #pragma unroll
            for (int half = 0; half < 2; half++) {
                int row = rbase + mt * 16 + half * 8;
                if (row >= NN) continue;
                #pragma unroll
                for (int nt = 0; nt < 8; nt++) {
                    int col = cbase + nt * 8;
                    float2 o;
                    o.x = acc[mt][nt][half * 2 + 0] + s_vec[col];
                    o.y = acc[mt][nt][half * 2 + 1] + s_vec[col + 1];
                    *(float2*)&g_z[(size_t)row * 512 + bn0 + col] = o;
                }
            }
    } else {
        float pa[2][2][2], pd[2][2][2];
        #pragma unroll
        for (int mt = 0; mt < 2; mt++)
            #pragma unroll
            for (int half = 0; half < 2; half++) {
                pa[mt][half][0] = pa[mt][half][1] = 0.f;
                pd[mt][half][0] = pd[mt][half][1] = 0.f;
            }
        #pragma unroll
        for (int mt = 0; mt < 2; mt++)
            #pragma unroll
            for (int half = 0; half < 2; half++) {
                int row = rbase + mt * 16 + half * 8;
                bool ok = row < NN;
                #pragma unroll
                for (int nt = 0; nt < 8; nt++) {
                    int col = cbase + nt * 8;
                    float v0 = acc[mt][nt][half * 2 + 0];
                    float v1 = acc[mt][nt][half * 2 + 1];
                    if (ok) *(float2*)&g_xp[(size_t)row * 128 + col] = make_float2(v0, v1);
                    int hh = nt >> 2;
                    pa[mt][half][hh] += v0 * s_vec[col] + v1 * s_vec[col + 1];
                    pd[mt][half][hh] += v0 * s_vec[128 + col] + v1 * s_vec[128 + col + 1];
                }
            }
        #pragma unroll
        for (int mt = 0; mt < 2; mt++)
            #pragma unroll
            for (int half = 0; half < 2; half++)
                #pragma unroll
                for (int hh = 0; hh < 2; hh++) {
                    float a = pa[mt][half][hh], d = pd[mt][half][hh];
                    a += __shfl_xor_sync(0xffffffffu, a, 1);
                    a += __shfl_xor_sync(0xffffffffu, a, 2);
                    d += __shfl_xor_sync(0xffffffffu, d, 1);
                    d += __shfl_xor_sync(0xffffffffu, d, 2);
                    if ((lane & 3) == 0) {
                        int row = rbase + mt * 16 + half * 8;
                        if (row < NN) {
                            int head = warpn * 2 + hh;
                            g_asrc[row * 4 + head] = a;
                            g_adst[row * 4 + head] = d;
                        }
                    }
                }
    }
}

// ---------------- segment softmax + aggregate + bias + residual + LN + ReLU -
__global__ void __launch_bounds__(256) k_aggr(const float* __restrict__ gb,
                                              const float* __restrict__ lg,
                                              const float* __restrict__ lb) {
    int w = threadIdx.x >> 5, lane = threadIdx.x & 31;
    int n = blockIdx.x * 8 + w;
    if (n >= NN) return;
    int h = lane >> 3;
    int hh = lane & 3;
    int s0 = g_rowptr[n], s1 = g_rowptr[n + 1];

    float adhh = g_adst[n * 4 + hh];
    float mx = -1e30f;
    for (int i = s0 + (lane >> 2); i < s1; i += 8) {
        int s = g_csrsrc[i];
        float v = g_asrc[s * 4 + hh] + adhh;
        v = v > 0.f ? v : 0.2f * v;
        mx = fmaxf(mx, v);
    }
    mx = fmaxf(mx, __shfl_xor_sync(0xffffffffu, mx, 4));
    mx = fmaxf(mx, __shfl_xor_sync(0xffffffffu, mx, 8));
    mx = fmaxf(mx, __shfl_xor_sync(0xffffffffu, mx, 16));
    float m_h = __shfl_sync(0xffffffffu, mx, h);
    float ad_h = __shfl_sync(0xffffffffu, adhh, h);

    float4 acc = make_float4(0.f, 0.f, 0.f, 0.f);
    float denom = 0.f;
    for (int i = s0; i < s1; i++) {
        int s = g_csrsrc[i];
        float v = g_asrc[s * 4 + h] + ad_h;
        v = v > 0.f ? v : 0.2f * v;
        float ex = __expf(v - m_h);
        denom += ex;
        float4 xv = *(const float4*)&g_xp[s * 128 + lane * 4];
        acc.x += ex * xv.x; acc.y += ex * xv.y;
        acc.z += ex * xv.z; acc.w += ex * xv.w;
    }
    float inv = 1.f / (denom + 1e-16f);
    int j = lane * 4;
    float4 hv = *(const float4*)&g_h[n * 128 + j];
    float4 bv = *(const float4*)&gb[j];
    float4 o;
    o.x = acc.x * inv + bv.x + hv.x;
    o.y = acc.y * inv + bv.y + hv.y;
    o.z = acc.z * inv + bv.z + hv.z;
    o.w = acc.w * inv + bv.w + hv.w;
    float sm = o.x + o.y + o.z + o.w;
    #pragma unroll
    for (int q = 16; q; q >>= 1) sm += __shfl_xor_sync(0xffffffffu, sm, q);
    float mu = sm * (1.f / 128.f);
    float dx = o.x - mu, dy = o.y - mu, dz = o.z - mu, dw = o.w - mu;
    float sq = dx * dx + dy * dy + dz * dz + dw * dw;
    #pragma unroll
    for (int q = 16; q; q >>= 1) sq += __shfl_xor_sync(0xffffffffu, sq, q);
    float rs = rsqrtf(sq * (1.f / 128.f) + 1e-5f);
    float4 gv = *(const float4*)&lg[j];
    float4 bb = *(const float4*)&lb[j];
    o.x = fmaxf(gv.x * dx * rs + bb.x, 0.f);
    o.y = fmaxf(gv.y * dy * rs + bb.y, 0.f);
    o.z = fmaxf(gv.z * dz * rs + bb.z, 0.f);
    o.w = fmaxf(gv.w * dw * rs + bb.w, 0.f);
    *(float4*)&g_h[n * 128 + j] = o;
}

// ---------------- LSTM gate nonlinearity ------------------------------------
__global__ void k_gates(int cell) {
    int idx = blockIdx.x * 256 + threadIdx.x;
    if (idx >= NN * HID) return;
    float* hq = cell ? g_h1 : g_h0;
    float* cq = cell ? g_c1 : g_c0;
    int n = idx >> 7, j = idx & 127;
    const float* z = g_z + (size_t)n * 512 + j;
    float zi = z[0], zf = z[128], zg = z[256], zo = z[384];
    float si = 1.f / (1.f + __expf(-zi));
    float sf = 1.f / (1.f + __expf(-zf));
    float so = 1.f / (1.f + __expf(-zo));
    float tg = tanhf(zg);
    float c = sf * cq[idx] + si * tg;
    float hh = so * tanhf(c);
    cq[idx] = c;
    hq[idx] = hh;
}

// ---------------- output head -----------------------------------------------
__global__ void k_out(const float* __restrict__ W1, const float* __restrict__ b1,
                      const float* __restrict__ W2, const float* __restrict__ b2,
                      float* __restrict__ out) {
    int w = threadIdx.x >> 5, lane = threadIdx.x & 31;
    int n = blockIdx.x * 8 + w;
    if (n >= NN) return;
    float a0 = b1[lane], a1 = b1[lane + 32];
    const float* hp = g_h1 + n * 128;
    #pragma unroll 4
    for (int k = 0; k < 128; k++) {
        float hk = hp[k];
        a0 += hk * W1[k * 64 + lane];
        a1 += hk * W1[k * 64 + lane + 32];
    }
    float s = fmaxf(a0, 0.f) * W2[lane] + fmaxf(a1, 0.f) * W2[lane + 32];
    #pragma unroll
    for (int q = 16; q; q >>= 1) s += __shfl_xor_sync(0xffffffffu, s, q);
    if (lane == 0) out[n] = s + b2[0];
}

// ---------------- driver -----------------------------------------------------
extern "C" void kernel_launch(void* const* d_in, const int* in_sizes, int n_in,
                              void* d_out, int out_size) {
    const float* xs    = (const float*)d_in[0];
    const float* xd    = (const float*)d_in[1];
    const int*   ei    = (const int*)d_in[2];
    const float* projW = (const float*)d_in[3];
    const float* projb = (const float*)d_in[4];
    const float* gatW  = (const float*)d_in[5];
    const float* attS  = (const float*)d_in[6];
    const float* attD  = (const float*)d_in[7];
    const float* gatb  = (const float*)d_in[8];
    const float* lng   = (const float*)d_in[9];
    const float* lnb   = (const float*)d_in[10];
    const float* Wih0  = (const float*)d_in[11];
    const float* Whh0  = (const float*)d_in[12];
    const float* bih0  = (const float*)d_in[13];
    const float* bhh0  = (const float*)d_in[14];
    const float* Wih1  = (const float*)d_in[15];
    const float* Whh1  = (const float*)d_in[16];
    const float* bih1  = (const float*)d_in[17];
    const float* bhh1  = (const float*)d_in[18];
    const float* oW1   = (const float*)d_in[19];
    const float* ob1   = (const float*)d_in[20];
    const float* oW2   = (const float*)d_in[21];
    const float* ob2   = (const float*)d_in[22];
    float* out = (float*)d_out;

    k_init<<<(NN * HID + 255) / 256, 256>>>();
    k_count<<<(EE + 255) / 256, 256>>>(ei);
    k_scan<<<1, 1024>>>();
    k_fill<<<(EP + 255) / 256, 256>>>(ei);
    k_prep_lstm<<<(512 * 256 + 255) / 256, 256>>>(Wih0, Whh0, Wih1, Whh1,
                                                  bih0, bhh0, bih1, bhh1);
    k_prep_gat<<<(NL * 128 * 128 + 255) / 256, 256>>>(gatW);

    const int MT = (NN + 127) / 128;  // 157
    for (int t = 0; t < TT; t++) {
        k_proj<<<NN / 16, 256>>>(xs, xd + (size_t)t * NN * DDIM, projW, projb);
        for (int l = 0; l < NL; l++) {
            k_mma<<<dim3(MT, 1), 256>>>(0, l, attS + l * HID, attD + l * HID);
            k_aggr<<<(NN + 7) / 8, 256>>>(gatb + l * HID, lng + l * HID, lnb + l * HID);
        }
        k_mma<<<dim3(MT, 4), 256>>>(1, 0, nullptr, nullptr);
        k_gates<<<(NN * HID + 255) / 256, 256>>>(0);
        k_mma<<<dim3(MT, 4), 256>>>(1, 1, nullptr, nullptr);
        k_gates<<<(NN * HID + 255) / 256, 256>>>(1);
    }
    k_out<<<(NN + 7) / 8, 256>>>(oW1, ob1, oW2, ob2, out);
}